// round 12
// baseline (speedup 1.0000x reference)
#include <cuda_runtime.h>
#include <cuda_fp16.h>
#include <cstdint>

#define NB 2
#define SEQ 2048
#define EMB 1024
#define NHEADS 16
#define NROWS (NB * SEQ)

// Scratch (__device__ globals per allocation rules)
__device__ __half g_wh[EMB * EMB];          // folded Wv/Wo fp16: [k'][n]
__device__ __half g_vh[NROWS * EMB];        // value as fp16
__device__ __half g_vch[NROWS * EMB];       // Vc = value @ Wcomb, fp16
__device__ __half g_afh[(long)NROWS * SEQ]; // binary mask fp16: 1.0 where mask==0
__device__ float  g_invcnt[NROWS];          // 1 / (# zeros in row), fp32

// ---------------------------------------------------------------------------
__device__ __forceinline__ void mma_f16(float c[4],
                                        uint32_t a0, uint32_t a1, uint32_t a2, uint32_t a3,
                                        uint32_t b0, uint32_t b1) {
    asm volatile(
        "mma.sync.aligned.m16n8k16.row.col.f32.f16.f16.f32 "
        "{%0,%1,%2,%3}, {%4,%5,%6,%7}, {%8,%9}, {%0,%1,%2,%3};"
        : "+f"(c[0]), "+f"(c[1]), "+f"(c[2]), "+f"(c[3])
        : "r"(a0), "r"(a1), "r"(a2), "r"(a3), "r"(b0), "r"(b1));
}

__device__ __forceinline__ void ldsm_x4(uint32_t& r0, uint32_t& r1,
                                        uint32_t& r2, uint32_t& r3, uint32_t addr) {
    asm volatile("ldmatrix.sync.aligned.m8n8.x4.shared.b16 {%0,%1,%2,%3}, [%4];"
                 : "=r"(r0), "=r"(r1), "=r"(r2), "=r"(r3) : "r"(addr));
}
__device__ __forceinline__ void ldsm_x4_t(uint32_t& r0, uint32_t& r1,
                                          uint32_t& r2, uint32_t& r3, uint32_t addr) {
    asm volatile("ldmatrix.sync.aligned.m8n8.x4.trans.shared.b16 {%0,%1,%2,%3}, [%4];"
                 : "=r"(r0), "=r"(r1), "=r"(r2), "=r"(r3) : "r"(addr));
}

__device__ __forceinline__ void cp16(uint32_t s, const void* g) {
    asm volatile("cp.async.cg.shared.global [%0], [%1], 16;" :: "r"(s), "l"(g));
}
__device__ __forceinline__ void cp_commit() { asm volatile("cp.async.commit_group;"); }
__device__ __forceinline__ void cp_wait0()  { asm volatile("cp.async.wait_group 0;"); }
__device__ __forceinline__ void cp_wait1()  { asm volatile("cp.async.wait_group 1;"); }
__device__ __forceinline__ void cp_wait2()  { asm volatile("cp.async.wait_group 2;"); }

// ---------------------------------------------------------------------------
// Prep kernel (slim): blocks [0,256) wcomb, [256,2304) value->fp16
// ---------------------------------------------------------------------------
__global__ __launch_bounds__(256) void prep_kernel(
    const float* __restrict__ value,
    const float* __restrict__ Wv, const float* __restrict__ Wo)
{
    const int b = blockIdx.x;
    const int tid = threadIdx.x;

    if (b < 256) {
        __shared__ float sWv[64][68];
        __shared__ float sWoT[64][68];
        const int h = b >> 4;
        const int n0 = (b & 15) * 64;

        for (int i = tid; i < 4096; i += 256) {
            int d = i >> 6, r = i & 63;
            sWv[d][r] = Wv[i];
        }
        for (int i = tid; i < 4096; i += 256) {
            int c = i >> 6, d = i & 63;
            sWoT[d][c] = Wo[(long)(n0 + c) * EMB + h * 64 + d];
        }
        __syncthreads();

        const int tr = (tid >> 4) * 4, tc = (tid & 15) * 4;
        float acc[4][4];
#pragma unroll
        for (int i = 0; i < 4; i++)
#pragma unroll
            for (int j = 0; j < 4; j++) acc[i][j] = 0.f;
#pragma unroll
        for (int d = 0; d < 64; d++) {
            float4 av = *(const float4*)&sWv[d][tr];
            float4 bv = *(const float4*)&sWoT[d][tc];
            float a[4] = {av.x, av.y, av.z, av.w};
            float bb[4] = {bv.x, bv.y, bv.z, bv.w};
#pragma unroll
            for (int i = 0; i < 4; i++)
#pragma unroll
                for (int j = 0; j < 4; j++) acc[i][j] += a[i] * bb[j];
        }
#pragma unroll
        for (int i = 0; i < 4; i++) {
            __half2 h0 = __floats2half2_rn(acc[i][0], acc[i][1]);
            __half2 h1 = __floats2half2_rn(acc[i][2], acc[i][3]);
            uint2 w = make_uint2(*(uint32_t*)&h0, *(uint32_t*)&h1);
            *(uint2*)(g_wh + (long)(h * 64 + tr + i) * EMB + n0 + tc) = w;
        }
    } else {
        long i0 = (long)(b - 256) * 512 + tid;
#pragma unroll
        for (int u = 0; u < 2; u++) {
            long i = i0 + u * 256;
            float4 v = ((const float4*)value)[i];
            __half2 h0 = __floats2half2_rn(v.x, v.y);
            __half2 h1 = __floats2half2_rn(v.z, v.w);
            ((uint2*)g_vh)[i] = make_uint2(*(uint32_t*)&h0, *(uint32_t*)&h1);
        }
    }
}

// ---------------------------------------------------------------------------
// fp16 GEMM core (template over BN, thread count). Block M=128, BK=32,
// warp tile 64x32, m16n8k16, ldmatrix A(x4)/B(x4.trans), NSTG=4 cp.async.
// A smem: 128 rows x 40 halves (pad). B smem: [32][BN], chunk swizzle cc^(r&7).
// ---------------------------------------------------------------------------
#define BM 128
#define BK 32
#define NSTG 4
#define A_BYTES (BM * 40 * 2)

template <int BN_, int NT_>
__device__ __forceinline__ void gemm_core_h(const __half* Ab, long astride,
                                            const __half* Bb,
                                            float acc[4][4][4], int nIter)
{
    constexpr int B_BYTES_ = BK * BN_ * 2;
    extern __shared__ char smh[];
    uint32_t sA = (uint32_t)__cvta_generic_to_shared(smh);
    uint32_t sB = sA + NSTG * A_BYTES;

    const int tid = threadIdx.x;
    const int wid = tid >> 5, lane = tid & 31;
    constexpr int NW_N = BN_ / 32;
    const int wm = (wid / NW_N) * 64;
    const int wn = (wid % NW_N) * 32;

    const int lrow = lane & 15;
    const int lk8 = (lane & 16) >> 1;
    const int bhi = (lane >> 4) & 1;

    uint32_t aoff[4];
#pragma unroll
    for (int mt = 0; mt < 4; mt++)
        aoff[mt] = (uint32_t)((wm + mt * 16 + lrow) * 40 + lk8) * 2;

    auto load_tiles = [&](int k0, int st) {
#pragma unroll
        for (int ch = tid; ch < 512; ch += NT_) {
            int r = ch >> 2, cc = ch & 3;
            cp16(sA + (uint32_t)(st * A_BYTES) + (uint32_t)(r * 40 + cc * 8) * 2,
                 Ab + (long)r * astride + k0 + cc * 8);
        }
#pragma unroll
        for (int ch = tid; ch < 4 * BN_; ch += NT_) {
            int r = ch / (BN_ / 8), cc = ch % (BN_ / 8);
            cp16(sB + (uint32_t)(st * B_BYTES_) +
                     (uint32_t)(r * BN_ + ((cc ^ (r & 7)) * 8)) * 2,
                 Bb + (long)(k0 + r) * EMB + cc * 8);
        }
        cp_commit();
    };

    load_tiles(0, 0);
    load_tiles(BK, 1);
    load_tiles(2 * BK, 2);

    for (int i = 0; i < nIter; i++) {
        const int rem = nIter - 1 - i;
        if (rem >= 2) cp_wait2();
        else if (rem == 1) cp_wait1();
        else cp_wait0();
        __syncthreads();
        if (i + 3 < nIter) load_tiles((i + 3) * BK, (i + 3) % NSTG);

        const int st = i % NSTG;
        const uint32_t aS = sA + (uint32_t)(st * A_BYTES);
        const uint32_t bS = sB + (uint32_t)(st * B_BYTES_);

#pragma unroll
        for (int ks = 0; ks < 2; ks++) {
            const int kb = ks * 16;
            uint32_t a[4][4], br[2][4];
#pragma unroll
            for (int mt = 0; mt < 4; mt++)
                ldsm_x4(a[mt][0], a[mt][1], a[mt][2], a[mt][3],
                        aS + aoff[mt] + kb * 2);
#pragma unroll
            for (int nt2 = 0; nt2 < 2; nt2++) {
                int krow = kb + lrow;
                int nc = ((wn + nt2 * 16) >> 3) + bhi;
                int cs = nc ^ (krow & 7);
                ldsm_x4_t(br[nt2][0], br[nt2][1], br[nt2][2], br[nt2][3],
                          bS + (uint32_t)(krow * BN_ + cs * 8) * 2);
            }
#pragma unroll
            for (int mt = 0; mt < 4; mt++)
#pragma unroll
                for (int nt = 0; nt < 4; nt++) {
                    int nt2 = nt >> 1, pr = (nt & 1) * 2;
                    mma_f16(acc[mt][nt], a[mt][0], a[mt][1], a[mt][2], a[mt][3],
                            br[nt2][pr], br[nt2][pr + 1]);
                }
        }
    }
}

// ---------------------------------------------------------------------------
// Hybrid kernel: blocks [0,256) = Vc GEMM tiles; blocks [256,2304) = maskf
// (2 rows each). Mask traffic overlaps vc tensor work in spare CTA slots.
// ---------------------------------------------------------------------------
#define VC_SMEM (NSTG * (A_BYTES + BK * 128 * 2))    // 73728

__global__ __launch_bounds__(256, 2) void vcmask_kernel(const int* __restrict__ mask)
{
    const int b = blockIdx.x;
    const int tid = threadIdx.x;

    if (b >= 256) {
        // ---- maskf: 2 rows per block
        extern __shared__ char smh[];
        int* ws = (int*)smh;
        const uint32_t ONE = 0x3C00u;
#pragma unroll
        for (int rr = 0; rr < 2; rr++) {
            const int row = (b - 256) * 2 + rr;
            const long base = (long)row * SEQ;
            const int4* mp = (const int4*)(mask + base);

            int4 a = mp[tid];
            int4 bb = mp[tid + 256];
            int c = (a.x == 0) + (a.y == 0) + (a.z == 0) + (a.w == 0)
                  + (bb.x == 0) + (bb.y == 0) + (bb.z == 0) + (bb.w == 0);
#pragma unroll
            for (int off = 16; off > 0; off >>= 1)
                c += __shfl_down_sync(0xffffffffu, c, off);
            if ((tid & 31) == 0) ws[rr * 8 + (tid >> 5)] = c;

            uint2 w0, w1;
            w0.x = ((a.x == 0) ? ONE : 0u) | (((a.y == 0) ? ONE : 0u) << 16);
            w0.y = ((a.z == 0) ? ONE : 0u) | (((a.w == 0) ? ONE : 0u) << 16);
            w1.x = ((bb.x == 0) ? ONE : 0u) | (((bb.y == 0) ? ONE : 0u) << 16);
            w1.y = ((bb.z == 0) ? ONE : 0u) | (((bb.w == 0) ? ONE : 0u) << 16);
            *(uint2*)(g_afh + base + tid * 4) = w0;
            *(uint2*)(g_afh + base + 1024 + tid * 4) = w1;
        }
        __syncthreads();
        if (tid < 2) {
            int t = 0;
#pragma unroll
            for (int i = 0; i < 8; i++) t += ws[tid * 8 + i];
            g_invcnt[(b - 256) * 2 + tid] = 1.0f / (float)t;
        }
        return;
    }

    // ---- Vc GEMM tile: e0 = (b&7)*128, row0 = (b>>3)*128
    const int wid = tid >> 5, lane = tid & 31;
    const int gid = lane >> 2, tig = lane & 3;
    const int wm = (wid >> 2) * 64;
    const int wn = (wid & 3) * 32;

    const int e0 = (b & 7) * 128;
    const int row0 = (b >> 3) * BM;

    float acc[4][4][4];
#pragma unroll
    for (int a = 0; a < 4; a++)
#pragma unroll
        for (int bb = 0; bb < 4; bb++)
#pragma unroll
            for (int c = 0; c < 4; c++) acc[a][bb][c] = 0.f;

    gemm_core_h<128, 256>(g_vh + (long)row0 * EMB, EMB, g_wh + e0, acc, EMB / BK);

#pragma unroll
    for (int mt = 0; mt < 4; mt++) {
        int r0a = row0 + wm + mt * 16 + gid;
#pragma unroll
        for (int nt = 0; nt < 4; nt++) {
            int col = e0 + wn + nt * 8 + 2 * tig;
            __half2 h0 = __floats2half2_rn(acc[mt][nt][0], acc[mt][nt][1]);
            __half2 h1 = __floats2half2_rn(acc[mt][nt][2], acc[mt][nt][3]);
            *(__half2*)(g_vch + (long)r0a * EMB + col) = h0;
            *(__half2*)(g_vch + (long)(r0a + 8) * EMB + col) = h1;
        }
    }
}

// ---------------------------------------------------------------------------
// Kernel: out = diag(invcnt) * (g_afh @ g_vch) + bo
// BN=256, 512 threads (16 warps, 2m x 8n), 1 CTA/SM, grid (4,32)=128 balanced.
// ---------------------------------------------------------------------------
#define MS_SMEM (NSTG * (A_BYTES + BK * 256 * 2))    // 106496

__global__ __launch_bounds__(512, 1) void masked_gemm_kernel(
    const float* __restrict__ bo, float* __restrict__ Y)
{
    const int tid = threadIdx.x;
    const int wid = tid >> 5, lane = tid & 31;
    const int gid = lane >> 2, tig = lane & 3;
    const int wm = (wid >> 3) * 64;
    const int wn = (wid & 7) * 32;

    const int e0 = blockIdx.x * 256;
    const int row0 = blockIdx.y * BM;
    const int n = row0 / SEQ;

    float acc[4][4][4];
#pragma unroll
    for (int a = 0; a < 4; a++)
#pragma unroll
        for (int b = 0; b < 4; b++)
#pragma unroll
            for (int c = 0; c < 4; c++) acc[a][b][c] = 0.f;

    gemm_core_h<256, 512>(g_afh + (long)row0 * SEQ, SEQ,
                          g_vch + (long)n * SEQ * EMB + e0, acc, SEQ / BK);

#pragma unroll
    for (int mt = 0; mt < 4; mt++) {
        int r0a = row0 + wm + mt * 16 + gid;
        float s0 = g_invcnt[r0a];
        float s1 = g_invcnt[r0a + 8];
#pragma unroll
        for (int nt = 0; nt < 4; nt++) {
            int col = e0 + wn + nt * 8 + 2 * tig;
            float b0v = bo[col], b1v = bo[col + 1];
            float2 v0 = make_float2(acc[mt][nt][0] * s0 + b0v, acc[mt][nt][1] * s0 + b1v);
            float2 v1 = make_float2(acc[mt][nt][2] * s1 + b0v, acc[mt][nt][3] * s1 + b1v);
            *(float2*)(Y + (long)r0a * EMB + col) = v0;
            *(float2*)(Y + (long)(r0a + 8) * EMB + col) = v1;
        }
    }
}

// ---------------------------------------------------------------------------
extern "C" void kernel_launch(void* const* d_in, const int* in_sizes, int n_in,
                              void* d_out, int out_size)
{
    const float* value = (const float*)d_in[0];
    // key/query/Wk/Wq unused: masked_fill(+1e20) before softmax forces all
    // unmasked scores to underflow; output is the masked average of projected V.
    const int*   mask  = (const int*)d_in[3];
    const float* Wv    = (const float*)d_in[4];
    const float* Wo    = (const float*)d_in[7];
    const float* bo    = (const float*)d_in[8];
    float* out = (float*)d_out;

    cudaFuncSetAttribute(vcmask_kernel,
                         cudaFuncAttributeMaxDynamicSharedMemorySize, VC_SMEM);
    cudaFuncSetAttribute(masked_gemm_kernel,
                         cudaFuncAttributeMaxDynamicSharedMemorySize, MS_SMEM);

    prep_kernel<<<2304, 256>>>(value, Wv, Wo);
    vcmask_kernel<<<256 + 2048, 256, VC_SMEM>>>(mask);
    {
        dim3 grid(EMB / 256, NROWS / BM);
        masked_gemm_kernel<<<grid, 512, MS_SMEM>>>(bo, out);
    }
}